// round 1
// baseline (speedup 1.0000x reference)
#include <cuda_runtime.h>
#include <math.h>

// Problem constants
#define B 64
#define J 2048
#define I 16
#define N 32
#define D 16
#define ND 512           // N*D
#define EPS 1e-7f

// u_hat layout: [b][j][q] with q = d*32 + n  (so lane=n is contiguous per d)
__device__ float g_uhat[(size_t)B * J * ND];     // 256 MiB
__device__ float g_b1[(size_t)B * J * N];        // 16 MiB, layout [b][j][n]
__device__ float g_spart[3][B * ND];             // s partials, layout [b][n*16+d]
__device__ float g_v[2][B * N * D];              // v0, v1

// ---------------------------------------------------------------------------
// Zero the atomic-accumulation buffers (must run every replay)
// ---------------------------------------------------------------------------
__global__ void zero_spart_kernel() {
    int t = blockIdx.x * blockDim.x + threadIdx.x;
    if (t < 3 * B * ND) ((float*)g_spart)[t] = 0.0f;
}

// ---------------------------------------------------------------------------
// K1: u_hat[b][j][q] = sum_i W[n,j,d,i] * x[b,j,i],  q = d*32+n
//     Also accumulates s0[b][nd] = sum_j u_hat (iter-0 c is uniform 1/32;
//     the 1/32 is applied in the squash kernel).
// grid = (J/32, ND/256), block = 256 threads (tx=32, ty=8)
// thread tile: 8 b-rows x 8 q-cols per j
// ---------------------------------------------------------------------------
#define JT 32
#define NDT 256

__global__ void __launch_bounds__(256)
k1_uhat_kernel(const float* __restrict__ x, const float* __restrict__ W) {
    __shared__ __align__(16) float Wsh[16][260];  // [i][q_local], padded pitch
    __shared__ __align__(16) float xsh[16][68];   // [i][b], padded pitch

    const int tx = threadIdx.x & 31;
    const int ty = threadIdx.x >> 5;
    const int j0 = blockIdx.x * JT;
    const int nd0 = blockIdx.y * NDT;

    float s0a[8][8];
#pragma unroll
    for (int r = 0; r < 8; ++r)
#pragma unroll
        for (int c = 0; c < 8; ++c) s0a[r][c] = 0.0f;

    for (int jj = 0; jj < JT; ++jj) {
        const int j = j0 + jj;
        __syncthreads();
        // Load W slice for this j: Wsh[i][ql] = W[n=(nd0+ql)&31, j, d=(nd0+ql)>>5, i]
#pragma unroll
        for (int k = 0; k < 16; ++k) {
            int e = (k << 8) + threadIdx.x;   // 0..4095
            int ql = e >> 4;
            int i  = e & 15;
            int q  = nd0 + ql;
            int n  = q & 31;
            int d  = q >> 5;
            Wsh[i][ql] = W[((n * J + j) << 8) + (d << 4) + i];
        }
        // Load x slice: xsh[i][b] = x[b, j, i]
#pragma unroll
        for (int k = 0; k < 4; ++k) {
            int e  = (k << 8) + threadIdx.x;  // 0..1023
            int bb = e >> 4;
            int i  = e & 15;
            xsh[i][bb] = x[((bb * J + j) << 4) + i];
        }
        __syncthreads();

        float acc[8][8];
#pragma unroll
        for (int r = 0; r < 8; ++r)
#pragma unroll
            for (int c = 0; c < 8; ++c) acc[r][c] = 0.0f;

#pragma unroll 4
        for (int i = 0; i < 16; ++i) {
            const float4 x0 = *reinterpret_cast<const float4*>(&xsh[i][ty * 8]);
            const float4 x1 = *reinterpret_cast<const float4*>(&xsh[i][ty * 8 + 4]);
            const float4 w0 = *reinterpret_cast<const float4*>(&Wsh[i][tx * 8]);
            const float4 w1 = *reinterpret_cast<const float4*>(&Wsh[i][tx * 8 + 4]);
            const float xr[8] = {x0.x, x0.y, x0.z, x0.w, x1.x, x1.y, x1.z, x1.w};
            const float wr[8] = {w0.x, w0.y, w0.z, w0.w, w1.x, w1.y, w1.z, w1.w};
#pragma unroll
            for (int r = 0; r < 8; ++r)
#pragma unroll
                for (int c = 0; c < 8; ++c)
                    acc[r][c] = fmaf(xr[r], wr[c], acc[r][c]);
        }

        // Write u_hat + accumulate s0
#pragma unroll
        for (int r = 0; r < 8; ++r) {
            const int b = ty * 8 + r;
            float* up = g_uhat + (((size_t)(b * J + j)) << 9) + nd0 + tx * 8;
            float4 o0 = make_float4(acc[r][0], acc[r][1], acc[r][2], acc[r][3]);
            float4 o1 = make_float4(acc[r][4], acc[r][5], acc[r][6], acc[r][7]);
            *reinterpret_cast<float4*>(up)     = o0;
            *reinterpret_cast<float4*>(up + 4) = o1;
#pragma unroll
            for (int c = 0; c < 8; ++c) s0a[r][c] += acc[r][c];
        }
    }

    // Flush s0 partials (convert q = d*32+n -> index n*16+d)
#pragma unroll
    for (int r = 0; r < 8; ++r) {
        const int b = ty * 8 + r;
#pragma unroll
        for (int c = 0; c < 8; ++c) {
            int q = nd0 + tx * 8 + c;
            int n = q & 31;
            int d = q >> 5;
            atomicAdd(&g_spart[0][b * ND + n * 16 + d], s0a[r][c]);
        }
    }
}

// ---------------------------------------------------------------------------
// Squash kernels: v = squash(pre * s).  One thread per (b,n).
// ---------------------------------------------------------------------------
__device__ __forceinline__ void squash_core(const float* s, float* out, float pre) {
    float sv[16];
    float s2 = 0.0f;
#pragma unroll
    for (int d = 0; d < 16; ++d) {
        float val = s[d] * pre;
        sv[d] = val;
        s2 = fmaf(val, val, s2);
    }
    s2 += EPS;
    float sc = sqrtf(s2) / (1.0f + s2);
#pragma unroll
    for (int d = 0; d < 16; ++d) out[d] = sc * sv[d];
}

template <int IT>
__global__ void squash_mid_kernel() {
    int t = blockIdx.x * blockDim.x + threadIdx.x;  // (b*32+n), 0..2047
    const float pre = (IT == 0) ? (1.0f / 32.0f) : 1.0f;
    squash_core(&g_spart[IT][t * 16], &g_v[IT][t * 16], pre);
}

__global__ void squash_out_kernel(float* __restrict__ out) {
    int t = blockIdx.x * blockDim.x + threadIdx.x;
    squash_core(&g_spart[2][t * 16], &out[t * 16], 1.0f);
}

// ---------------------------------------------------------------------------
// Routing pass. MODE 1: b_prev = 0, writes b1.  MODE 2: reads b1, no write.
// grid = (B, 8), block = 256 (8 warps). warp handles 32 j's; lane = n.
// u_hat slab per (b,j) is 2KB, loads are 16 fully-coalesced 128B lines.
// ---------------------------------------------------------------------------
template <int MODE>
__global__ void __launch_bounds__(256)
route_kernel() {
    const int b = blockIdx.x;
    const int chunk = blockIdx.y;
    const int w = threadIdx.x >> 5;
    const int lane = threadIdx.x & 31;  // lane = n

    const float* vprev = g_v[MODE - 1];
    float vr[16];
#pragma unroll
    for (int d = 0; d < 16; ++d) vr[d] = vprev[(b * 32 + lane) * 16 + d];

    float acc[16];
#pragma unroll
    for (int d = 0; d < 16; ++d) acc[d] = 0.0f;

    const int jbase = chunk * 256 + w * 32;
    const float* ub = g_uhat + (((size_t)(b * J + jbase)) << 9);
    float* bb = g_b1 + (((size_t)(b * J + jbase)) << 5);

#pragma unroll 2
    for (int k = 0; k < 32; ++k) {
        const float* up = ub + (k << 9);
        float u[16];
#pragma unroll
        for (int d = 0; d < 16; ++d) u[d] = up[d * 32 + lane];

        float t = 0.0f;
#pragma unroll
        for (int d = 0; d < 16; ++d) t = fmaf(vr[d], u[d], t);

        if (MODE == 2) {
            t += bb[(k << 5) + lane];
        } else {
            bb[(k << 5) + lane] = t;
        }

        // softmax over the 32 lanes (= over n)
        float m = t;
#pragma unroll
        for (int s = 16; s > 0; s >>= 1)
            m = fmaxf(m, __shfl_xor_sync(0xffffffffu, m, s));
        float e = __expf(t - m);
        float sum = e;
#pragma unroll
        for (int s = 16; s > 0; s >>= 1)
            sum += __shfl_xor_sync(0xffffffffu, sum, s);
        float c = e / sum;

#pragma unroll
        for (int d = 0; d < 16; ++d) acc[d] = fmaf(c, u[d], acc[d]);
    }

    // Reduce across the 8 warps, then one atomicAdd per (n,d) per block
    __shared__ float red[8][512];
#pragma unroll
    for (int d = 0; d < 16; ++d) red[w][lane * 16 + d] = acc[d];
    __syncthreads();

    float* spart = g_spart[MODE];
    for (int idx = threadIdx.x; idx < 512; idx += 256) {
        float s = 0.0f;
#pragma unroll
        for (int ww = 0; ww < 8; ++ww) s += red[ww][idx];
        atomicAdd(&spart[b * ND + idx], s);
    }
}

// ---------------------------------------------------------------------------
// Launch
// ---------------------------------------------------------------------------
extern "C" void kernel_launch(void* const* d_in, const int* in_sizes, int n_in,
                              void* d_out, int out_size) {
    const float* x = (const float*)d_in[0];  // [B, J, I]
    const float* W = (const float*)d_in[1];  // [N, J, D, I]
    float* out = (float*)d_out;              // [B, N, D]

    zero_spart_kernel<<<96, 1024>>>();                    // 3*64*512 = 98304
    k1_uhat_kernel<<<dim3(J / JT, ND / NDT), 256>>>(x, W);
    squash_mid_kernel<0><<<16, 128>>>();                  // v0
    route_kernel<1><<<dim3(B, 8), 256>>>();               // iter 1 -> s1, b1
    squash_mid_kernel<1><<<16, 128>>>();                  // v1
    route_kernel<2><<<dim3(B, 8), 256>>>();               // iter 2 -> s2
    squash_out_kernel<<<16, 128>>>(out);                  // v2
}

// round 2
// speedup vs baseline: 1.2285x; 1.2285x over previous
#include <cuda_runtime.h>
#include <cuda_fp16.h>
#include <math.h>

#define B 64
#define J 2048
#define N 32
#define D 16
#define ND 512
#define EPS 1e-7f

// u_hat stored fp16: per (b,j) one 1KB row = 64 uint4; index ((b*J+j)*2+g)*32+n,
// uint4 = 8 halves = d in [g*8, g*8+8) for capsule n.
__device__ __align__(16) uint4 g_uhat4[(size_t)B * J * 64];   // 128 MiB
__device__ float g_b1[(size_t)B * J * N];                      // 16 MiB, [b][j][n]
__device__ float g_spart[3][B * ND];                           // s accum, [b][n*16+d]
__device__ float g_v[2][B * ND];                               // v0, v1

// ---- packed f32x2 helpers -------------------------------------------------
static __device__ __forceinline__ unsigned long long pk2(float a, float b) {
    unsigned long long v;
    asm("mov.b64 %0, {%1, %2};" : "=l"(v) : "f"(a), "f"(b));
    return v;
}
static __device__ __forceinline__ float2 upk2(unsigned long long v) {
    float2 f;
    asm("mov.b64 {%0, %1}, %2;" : "=f"(f.x), "=f"(f.y) : "l"(v));
    return f;
}
static __device__ __forceinline__ void fma2(unsigned long long& d,
                                            unsigned long long a,
                                            unsigned long long b) {
    asm("fma.rn.f32x2 %0, %1, %2, %0;" : "+l"(d) : "l"(a), "l"(b));
}
static __device__ __forceinline__ void add2(unsigned long long& d, unsigned long long a) {
    asm("add.rn.f32x2 %0, %0, %1;" : "+l"(d) : "l"(a));
}

// ---------------------------------------------------------------------------
__global__ void zero_spart_kernel() {
    int t = blockIdx.x * blockDim.x + threadIdx.x;
    if (t < 3 * B * ND) ((float*)g_spart)[t] = 0.0f;
}

// ---------------------------------------------------------------------------
// K1: u_hat[b,j,n,d] = sum_i W[n,j,d,i] x[b,j,i] -> fp16, plus fused s0 accum.
// grid (J/8, 2): blockIdx.y = g (d-half). block 512: tx=n (32), ty=b-group (16x4).
// ---------------------------------------------------------------------------
#define JT1 8
__global__ void __launch_bounds__(512, 1)
k1_kernel(const float* __restrict__ x, const float* __restrict__ W) {
    __shared__ __align__(16) float Wsh[16][260];  // [i][n*8+dd]
    __shared__ float xsh[16][68];                 // [i][b]

    const int tid = threadIdx.x;
    const int tx = tid & 31;       // n
    const int ty = tid >> 5;       // 0..15 -> 4 b's each
    const int g = blockIdx.y;      // d half: d = g*8 + dd
    const int j0 = blockIdx.x * JT1;

    unsigned long long s0a[4][4];
#pragma unroll
    for (int r = 0; r < 4; ++r)
#pragma unroll
        for (int c = 0; c < 4; ++c) s0a[r][c] = 0ull;

    for (int jj = 0; jj < JT1; ++jj) {
        const int j = j0 + jj;
        __syncthreads();
        // W slice: 32 n x 8 d x 16 i = 4096 floats, coalesced (512B chunks per n)
#pragma unroll
        for (int k = 0; k < 8; ++k) {
            int e = (k << 9) + tid;            // 0..4095
            int n = e >> 7;
            int inner = e & 127;               // dd*16 + i
            Wsh[inner & 15][(n << 3) + (inner >> 4)] =
                W[((n * J + j) << 8) + (g << 7) + inner];
        }
        // x slice: 64 b x 16 i
#pragma unroll
        for (int k = 0; k < 2; ++k) {
            int e = (k << 9) + tid;
            xsh[e & 15][e >> 4] = x[(((e >> 4) * J + j) << 4) + (e & 15)];
        }
        __syncthreads();

        unsigned long long acc[4][4];
#pragma unroll
        for (int r = 0; r < 4; ++r)
#pragma unroll
            for (int c = 0; c < 4; ++c) acc[r][c] = 0ull;

#pragma unroll
        for (int i = 0; i < 16; ++i) {
            ulonglong2 wA = *reinterpret_cast<const ulonglong2*>(&Wsh[i][tx * 8]);
            ulonglong2 wB = *reinterpret_cast<const ulonglong2*>(&Wsh[i][tx * 8 + 4]);
            unsigned long long wp0 = wA.x, wp1 = wA.y, wp2 = wB.x, wp3 = wB.y;
#pragma unroll
            for (int r = 0; r < 4; ++r) {
                float xv = xsh[i][ty * 4 + r];
                unsigned long long xp = pk2(xv, xv);
                fma2(acc[r][0], xp, wp0);
                fma2(acc[r][1], xp, wp1);
                fma2(acc[r][2], xp, wp2);
                fma2(acc[r][3], xp, wp3);
            }
        }

        // store fp16 + accumulate s0
#pragma unroll
        for (int r = 0; r < 4; ++r) {
            const int b = ty * 4 + r;
            float2 f0 = upk2(acc[r][0]);
            float2 f1 = upk2(acc[r][1]);
            float2 f2 = upk2(acc[r][2]);
            float2 f3 = upk2(acc[r][3]);
            __half2 h0 = __floats2half2_rn(f0.x, f0.y);
            __half2 h1 = __floats2half2_rn(f1.x, f1.y);
            __half2 h2 = __floats2half2_rn(f2.x, f2.y);
            __half2 h3 = __floats2half2_rn(f3.x, f3.y);
            uint4 o;
            o.x = *reinterpret_cast<unsigned*>(&h0);
            o.y = *reinterpret_cast<unsigned*>(&h1);
            o.z = *reinterpret_cast<unsigned*>(&h2);
            o.w = *reinterpret_cast<unsigned*>(&h3);
            g_uhat4[((size_t)(b * J + j) * 2 + g) * 32 + tx] = o;
#pragma unroll
            for (int c = 0; c < 4; ++c) add2(s0a[r][c], acc[r][c]);
        }
    }

    // flush s0 partials
#pragma unroll
    for (int r = 0; r < 4; ++r) {
        const int b = ty * 4 + r;
#pragma unroll
        for (int c = 0; c < 4; ++c) {
            float2 f = upk2(s0a[r][c]);
            int base = b * ND + tx * 16 + (g << 3) + c * 2;
            atomicAdd(&g_spart[0][base], f.x);
            atomicAdd(&g_spart[0][base + 1], f.y);
        }
    }
}

// ---------------------------------------------------------------------------
// Squash: v = squash(pre * s)
// ---------------------------------------------------------------------------
__device__ __forceinline__ void squash_core(const float* s, float* out, float pre) {
    float sv[16];
    float s2 = 0.0f;
#pragma unroll
    for (int d = 0; d < 16; ++d) {
        float val = s[d] * pre;
        sv[d] = val;
        s2 = fmaf(val, val, s2);
    }
    s2 += EPS;
    float sc = sqrtf(s2) / (1.0f + s2);
#pragma unroll
    for (int d = 0; d < 16; ++d) out[d] = sc * sv[d];
}

template <int IT>
__global__ void squash_mid_kernel() {
    int t = blockIdx.x * blockDim.x + threadIdx.x;  // (b*32+n)
    const float pre = (IT == 0) ? (1.0f / 32.0f) : 1.0f;
    squash_core(&g_spart[IT][t * 16], &g_v[IT][t * 16], pre);
}

__global__ void squash_out_kernel(float* __restrict__ out) {
    int t = blockIdx.x * blockDim.x + threadIdx.x;
    squash_core(&g_spart[2][t * 16], &out[t * 16], 1.0f);
}

// ---------------------------------------------------------------------------
// Routing pass. MODE 1: b_prev=0, writes b1. MODE 2: reads b1, no write.
// grid (B, 32), block 128 (4 warps); warp handles 16 j; lane = n.
// 2 fully coalesced uint4 loads per j (512B per warp-load), pipelined.
// ---------------------------------------------------------------------------
template <int MODE>
__global__ void __launch_bounds__(128)
route_kernel() {
    const int b = blockIdx.x;
    const int chunk = blockIdx.y;
    const int w = threadIdx.x >> 5;
    const int lane = threadIdx.x & 31;   // lane = n

    const float* vprev = g_v[MODE - 1];
    unsigned long long vr[8];
#pragma unroll
    for (int p = 0; p < 8; ++p) {
        float2 f = *reinterpret_cast<const float2*>(&vprev[(b * 32 + lane) * 16 + p * 2]);
        vr[p] = pk2(f.x, f.y);
    }

    unsigned long long acc[8];
#pragma unroll
    for (int p = 0; p < 8; ++p) acc[p] = 0ull;

    const int jbase = chunk * 64 + w * 16;
    const uint4* u4 = g_uhat4 + (size_t)(b * J + jbase) * 64;
    float* bb = g_b1 + (size_t)(b * J + jbase) * 32;

    uint4 A = __ldg(&u4[lane]);
    uint4 Bv = __ldg(&u4[32 + lane]);

#pragma unroll
    for (int k = 0; k < 16; ++k) {
        uint4 An, Bn;
        if (k < 15) {
            An = __ldg(&u4[(k + 1) * 64 + lane]);
            Bn = __ldg(&u4[(k + 1) * 64 + 32 + lane]);
        }

        unsigned long long up[8];
        const __half2* pa = reinterpret_cast<const __half2*>(&A);
        const __half2* pb = reinterpret_cast<const __half2*>(&Bv);
#pragma unroll
        for (int p = 0; p < 4; ++p) {
            float2 fa = __half22float2(pa[p]);
            float2 fb = __half22float2(pb[p]);
            up[p] = pk2(fa.x, fa.y);
            up[4 + p] = pk2(fb.x, fb.y);
        }

        unsigned long long t2 = 0ull;
#pragma unroll
        for (int p = 0; p < 8; ++p) fma2(t2, vr[p], up[p]);
        float2 ft = upk2(t2);
        float t = ft.x + ft.y;

        if (MODE == 2) t += __ldg(&bb[(k << 5) + lane]);
        else bb[(k << 5) + lane] = t;

        // softmax over n (32 lanes); logits bounded, no max pass needed
        float e = __expf(t);
        float sum = e;
#pragma unroll
        for (int s = 16; s > 0; s >>= 1)
            sum += __shfl_xor_sync(0xffffffffu, sum, s);
        float c = __fdividef(e, sum);

        unsigned long long c2 = pk2(c, c);
#pragma unroll
        for (int p = 0; p < 8; ++p) fma2(acc[p], c2, up[p]);

        A = An;
        Bv = Bn;
    }

    __shared__ float red[4][512];
#pragma unroll
    for (int p = 0; p < 8; ++p) {
        float2 f = upk2(acc[p]);
        red[w][lane * 16 + p * 2] = f.x;
        red[w][lane * 16 + p * 2 + 1] = f.y;
    }
    __syncthreads();

    float* spart = g_spart[MODE];
    for (int idx = threadIdx.x; idx < 512; idx += 128) {
        float s = red[0][idx] + red[1][idx] + red[2][idx] + red[3][idx];
        atomicAdd(&spart[b * ND + idx], s);
    }
}

// ---------------------------------------------------------------------------
extern "C" void kernel_launch(void* const* d_in, const int* in_sizes, int n_in,
                              void* d_out, int out_size) {
    const float* x = (const float*)d_in[0];  // [B, J, 16]
    const float* W = (const float*)d_in[1];  // [N, J, D, 16]
    float* out = (float*)d_out;              // [B, N, D]

    zero_spart_kernel<<<96, 1024>>>();
    k1_kernel<<<dim3(J / JT1, 2), 512>>>(x, W);
    squash_mid_kernel<0><<<16, 128>>>();
    route_kernel<1><<<dim3(B, 32), 128>>>();
    squash_mid_kernel<1><<<16, 128>>>();
    route_kernel<2><<<dim3(B, 32), 128>>>();
    squash_out_kernel<<<16, 128>>>(out);
}

// round 3
// speedup vs baseline: 1.3283x; 1.0812x over previous
#include <cuda_runtime.h>
#include <cuda_fp16.h>
#include <math.h>

#define B 64
#define J 2048
#define N 32
#define D 16
#define ND 512
#define EPS 1e-7f

// u_hat fp16: uint4 index ((b*J+j)*2+g)*32 + n ; uint4 = 8 halves, d in [8g,8g+8)
__device__ __align__(16) uint4 g_uhat4[(size_t)B * J * 64];       // 128 MiB
__device__ __align__(16) __half g_Wh[(size_t)N * J * D * 16];     // 33.5 MiB
__device__ __align__(16) __half g_xh[(size_t)B * J * 16];         // 4.2 MiB
__device__ float g_spart[3][B * ND];                              // s accum [b][r], r=n*16+d
__device__ float g_v[2][B * ND];                                  // v0, v0+v1

// ---- packed f32x2 helpers -------------------------------------------------
static __device__ __forceinline__ unsigned long long pk2(float a, float b) {
    unsigned long long v;
    asm("mov.b64 %0, {%1, %2};" : "=l"(v) : "f"(a), "f"(b));
    return v;
}
static __device__ __forceinline__ float2 upk2(unsigned long long v) {
    float2 f;
    asm("mov.b64 {%0, %1}, %2;" : "=f"(f.x), "=f"(f.y) : "l"(v));
    return f;
}
static __device__ __forceinline__ void fma2(unsigned long long& d,
                                            unsigned long long a,
                                            unsigned long long b) {
    asm("fma.rn.f32x2 %0, %1, %2, %0;" : "+l"(d) : "l"(a), "l"(b));
}

static __device__ __forceinline__ void mma16816(
    float& d0, float& d1, float& d2, float& d3,
    unsigned a0, unsigned a1, unsigned a2, unsigned a3,
    unsigned b0, unsigned b1,
    float c0, float c1, float c2, float c3) {
    asm volatile(
        "mma.sync.aligned.m16n8k16.row.col.f32.f16.f16.f32 "
        "{%0,%1,%2,%3},{%4,%5,%6,%7},{%8,%9},{%10,%11,%12,%13};"
        : "=f"(d0), "=f"(d1), "=f"(d2), "=f"(d3)
        : "r"(a0), "r"(a1), "r"(a2), "r"(a3), "r"(b0), "r"(b1),
          "f"(c0), "f"(c1), "f"(c2), "f"(c3));
}

// ---------------------------------------------------------------------------
__global__ void zero_spart_kernel() {
    int t = blockIdx.x * blockDim.x + threadIdx.x;
    if (t < 3 * B * ND) ((float*)g_spart)[t] = 0.0f;
}

// fp32 -> fp16 conversion kernels (grid sized exactly)
__global__ void cvt_w_kernel(const float4* __restrict__ src) {
    int t = blockIdx.x * blockDim.x + threadIdx.x;  // < 4194304
    float4 f = src[t];
    __half2 h0 = __floats2half2_rn(f.x, f.y);
    __half2 h1 = __floats2half2_rn(f.z, f.w);
    uint2 o;
    o.x = *reinterpret_cast<unsigned*>(&h0);
    o.y = *reinterpret_cast<unsigned*>(&h1);
    reinterpret_cast<uint2*>(g_Wh)[t] = o;
}
__global__ void cvt_x_kernel(const float4* __restrict__ src) {
    int t = blockIdx.x * blockDim.x + threadIdx.x;  // < 524288
    float4 f = src[t];
    __half2 h0 = __floats2half2_rn(f.x, f.y);
    __half2 h1 = __floats2half2_rn(f.z, f.w);
    uint2 o;
    o.x = *reinterpret_cast<unsigned*>(&h0);
    o.y = *reinterpret_cast<unsigned*>(&h1);
    reinterpret_cast<uint2*>(g_xh)[t] = o;
}

// ---------------------------------------------------------------------------
// K1 (tensor core): per j, C[64b x 512r] = x_j[64x16] * W_j[512x16]^T, fp32 acc.
// Stores per-j u_hat (fp16, as diff of running acc) and accumulates s0 over j
// in the mma C accumulators; flush with atomics at block end.
// grid (J/8, 2), block 256 (8 warps). warp w covers r in [by*256+w*32, +32).
// ---------------------------------------------------------------------------
#define K1_JT 8
__global__ void __launch_bounds__(256, 2) k1_mma_kernel() {
    const int w = threadIdx.x >> 5;
    const int lane = threadIdx.x & 31;
    const int gid = lane >> 2;   // 0..7
    const int tig = lane & 3;    // 0..3
    const int rbase = blockIdx.y * 256 + w * 32;
    const int j0 = blockIdx.x * K1_JT;

    float acc[4][4][4];  // [ri][mi][e]
#pragma unroll
    for (int ri = 0; ri < 4; ++ri)
#pragma unroll
        for (int mi = 0; mi < 4; ++mi)
#pragma unroll
            for (int e = 0; e < 4; ++e) acc[ri][mi][e] = 0.0f;

#pragma unroll 2
    for (int jj = 0; jj < K1_JT; ++jj) {
        const int j = j0 + jj;

        // A fragments (from global fp16 x, L1-resident): rows b, cols i
        unsigned a[4][4];
#pragma unroll
        for (int mi = 0; mi < 4; ++mi) {
            const __half* x0 = g_xh + (((size_t)((mi * 16 + gid) * J + j)) << 4);
            const __half* x1 = g_xh + (((size_t)((mi * 16 + gid + 8) * J + j)) << 4);
            a[mi][0] = *reinterpret_cast<const unsigned*>(x0 + 2 * tig);
            a[mi][1] = *reinterpret_cast<const unsigned*>(x1 + 2 * tig);
            a[mi][2] = *reinterpret_cast<const unsigned*>(x0 + 2 * tig + 8);
            a[mi][3] = *reinterpret_cast<const unsigned*>(x1 + 2 * tig + 8);
        }

#pragma unroll
        for (int ri = 0; ri < 4; ++ri) {
            // B fragment: B[k][c] = W_j[rt + c][k], c = gid, k = 2*tig(+1)(+8)
            const int rB = rbase + ri * 8 + gid;
            const int nB = rB >> 4, dB = rB & 15;
            const __half* wp = g_Wh + (((size_t)(nB * J + j)) << 8) + (dB << 4);
            const unsigned b0 = *reinterpret_cast<const unsigned*>(wp + 2 * tig);
            const unsigned b1 = *reinterpret_cast<const unsigned*>(wp + 2 * tig + 8);

            const int rt = rbase + ri * 8;
            const int nn = rt >> 4;
            const int g = (rt >> 3) & 1;

#pragma unroll
            for (int mi = 0; mi < 4; ++mi) {
                float d0, d1, d2, d3;
                mma16816(d0, d1, d2, d3,
                         a[mi][0], a[mi][1], a[mi][2], a[mi][3], b0, b1,
                         acc[ri][mi][0], acc[ri][mi][1], acc[ri][mi][2], acc[ri][mi][3]);
                const int brow = mi * 16 + gid;
                __half2 h01 = __floats2half2_rn(d0 - acc[ri][mi][0], d1 - acc[ri][mi][1]);
                __half2 h23 = __floats2half2_rn(d2 - acc[ri][mi][2], d3 - acc[ri][mi][3]);
                unsigned* outp = reinterpret_cast<unsigned*>(g_uhat4);
                size_t i01 = ((((size_t)(brow * J + j)) * 2 + g) * 32 + nn) * 4 + tig;
                size_t i23 = ((((size_t)((brow + 8) * J + j)) * 2 + g) * 32 + nn) * 4 + tig;
                outp[i01] = *reinterpret_cast<unsigned*>(&h01);
                outp[i23] = *reinterpret_cast<unsigned*>(&h23);
                acc[ri][mi][0] = d0; acc[ri][mi][1] = d1;
                acc[ri][mi][2] = d2; acc[ri][mi][3] = d3;
            }
        }
    }

    // flush s0 partials: c0/c1 at (brow, rC), (brow, rC+1); c2/c3 at brow+8
#pragma unroll
    for (int ri = 0; ri < 4; ++ri) {
        const int rC = rbase + ri * 8 + 2 * tig;
#pragma unroll
        for (int mi = 0; mi < 4; ++mi) {
            const int brow = mi * 16 + gid;
            atomicAdd(&g_spart[0][brow * ND + rC],           acc[ri][mi][0]);
            atomicAdd(&g_spart[0][brow * ND + rC + 1],       acc[ri][mi][1]);
            atomicAdd(&g_spart[0][(brow + 8) * ND + rC],     acc[ri][mi][2]);
            atomicAdd(&g_spart[0][(brow + 8) * ND + rC + 1], acc[ri][mi][3]);
        }
    }
}

// ---------------------------------------------------------------------------
// Squash: v = squash(pre * s)
// ---------------------------------------------------------------------------
__device__ __forceinline__ void squash_core(const float* s, float* out, float pre) {
    float sv[16];
    float s2 = 0.0f;
#pragma unroll
    for (int d = 0; d < 16; ++d) {
        float val = s[d] * pre;
        sv[d] = val;
        s2 = fmaf(val, val, s2);
    }
    s2 += EPS;
    float sc = sqrtf(s2) / (1.0f + s2);
#pragma unroll
    for (int d = 0; d < 16; ++d) out[d] = sc * sv[d];
}

template <int IT>
__global__ void squash_mid_kernel() {
    int t = blockIdx.x * blockDim.x + threadIdx.x;  // (b*32+n)
    if (IT == 0) {
        squash_core(&g_spart[0][t * 16], &g_v[0][t * 16], 1.0f / 32.0f);
    } else {
        float v1[16];
        squash_core(&g_spart[1][t * 16], v1, 1.0f);
#pragma unroll
        for (int d = 0; d < 16; ++d)
            g_v[1][t * 16 + d] = g_v[0][t * 16 + d] + v1[d];  // vsum = v0 + v1
    }
}

__global__ void squash_out_kernel(float* __restrict__ out) {
    int t = blockIdx.x * blockDim.x + threadIdx.x;
    squash_core(&g_spart[2][t * 16], &out[t * 16], 1.0f);
}

// ---------------------------------------------------------------------------
// Routing pass. MODE 1: logits = v0.u ; MODE 2: logits = (v0+v1).u (no b buf!)
// grid (B, 16), block 256 (8 warps); warp handles 16 j; lane = n.
// Pair-batched double-buffered prefetch: 8 uint4 in flight per warp.
// ---------------------------------------------------------------------------
__device__ __forceinline__ void route_j(const uint4& A, const uint4& Bv,
                                        const unsigned long long* vr,
                                        unsigned long long* acc) {
    unsigned long long up[8];
    const __half2* pa = reinterpret_cast<const __half2*>(&A);
    const __half2* pb = reinterpret_cast<const __half2*>(&Bv);
#pragma unroll
    for (int p = 0; p < 4; ++p) {
        float2 fa = __half22float2(pa[p]);
        float2 fb = __half22float2(pb[p]);
        up[p] = pk2(fa.x, fa.y);
        up[4 + p] = pk2(fb.x, fb.y);
    }
    unsigned long long t2 = 0ull;
#pragma unroll
    for (int p = 0; p < 8; ++p) fma2(t2, vr[p], up[p]);
    float2 ft = upk2(t2);
    float t = ft.x + ft.y;

    float e = __expf(t);
    float sum = e;
#pragma unroll
    for (int s = 16; s > 0; s >>= 1)
        sum += __shfl_xor_sync(0xffffffffu, sum, s);
    float c = __fdividef(e, sum);

    unsigned long long c2 = pk2(c, c);
#pragma unroll
    for (int p = 0; p < 8; ++p) fma2(acc[p], c2, up[p]);
}

template <int MODE>
__global__ void __launch_bounds__(256) route_kernel() {
    const int b = blockIdx.x;
    const int chunk = blockIdx.y;        // 0..15
    const int w = threadIdx.x >> 5;
    const int lane = threadIdx.x & 31;   // lane = n

    const float* vprev = g_v[MODE - 1];
    unsigned long long vr[8];
#pragma unroll
    for (int p = 0; p < 8; ++p) {
        float2 f = *reinterpret_cast<const float2*>(&vprev[(b * 32 + lane) * 16 + p * 2]);
        vr[p] = pk2(f.x, f.y);
    }

    unsigned long long acc[8];
#pragma unroll
    for (int p = 0; p < 8; ++p) acc[p] = 0ull;

    const int jbase = chunk * 128 + w * 16;
    const uint4* u4 = g_uhat4 + (size_t)(b * J + jbase) * 64;

    uint4 buf[2][4];
#pragma unroll
    for (int q = 0; q < 4; ++q) buf[0][q] = __ldg(&u4[q * 32 + lane]);

#pragma unroll
    for (int p = 0; p < 8; ++p) {
        const int cur = p & 1;
        if (p < 7) {
#pragma unroll
            for (int q = 0; q < 4; ++q)
                buf[cur ^ 1][q] = __ldg(&u4[(p + 1) * 128 + q * 32 + lane]);
        }
        route_j(buf[cur][0], buf[cur][1], vr, acc);
        route_j(buf[cur][2], buf[cur][3], vr, acc);
    }

    __shared__ float red[8][512];
#pragma unroll
    for (int p = 0; p < 8; ++p) {
        float2 f = upk2(acc[p]);
        red[w][lane * 16 + p * 2] = f.x;
        red[w][lane * 16 + p * 2 + 1] = f.y;
    }
    __syncthreads();

    float* spart = g_spart[MODE];
    for (int idx = threadIdx.x; idx < 512; idx += 256) {
        float s = 0.0f;
#pragma unroll
        for (int ww = 0; ww < 8; ++ww) s += red[ww][idx];
        atomicAdd(&spart[b * ND + idx], s);
    }
}

// ---------------------------------------------------------------------------
extern "C" void kernel_launch(void* const* d_in, const int* in_sizes, int n_in,
                              void* d_out, int out_size) {
    const float* x = (const float*)d_in[0];  // [B, J, 16]
    const float* W = (const float*)d_in[1];  // [N, J, D, 16]
    float* out = (float*)d_out;              // [B, N, D]

    cvt_w_kernel<<<16384, 256>>>((const float4*)W);   // 4,194,304 float4
    cvt_x_kernel<<<2048, 256>>>((const float4*)x);    // 524,288 float4
    zero_spart_kernel<<<96, 1024>>>();
    k1_mma_kernel<<<dim3(J / K1_JT, 2), 256>>>();
    squash_mid_kernel<0><<<16, 128>>>();              // v0
    route_kernel<1><<<dim3(B, 16), 256>>>();          // iter 1 -> s1
    squash_mid_kernel<1><<<16, 128>>>();              // vsum = v0+v1
    route_kernel<2><<<dim3(B, 16), 256>>>();          // iter 2 -> s2
    squash_out_kernel<<<16, 128>>>(out);              // v2
}

// round 4
// speedup vs baseline: 1.4490x; 1.0909x over previous
#include <cuda_runtime.h>
#include <cuda_fp16.h>
#include <math.h>

#define B 64
#define J 2048
#define N 32
#define D 16
#define ND 512
#define EPS 1e-7f

__device__ __align__(16) __half g_Wh[(size_t)N * J * D * 16];  // 33.5 MiB fp16 W
__device__ __align__(16) __half g_xh[(size_t)B * J * 16];      // 4.2 MiB fp16 x
__device__ float g_spart[3][B * ND];                            // s accum [b][n*16+d]
__device__ float g_v[2][B * ND];                                // v0, v0+v1

// ---- packed f32x2 helpers -------------------------------------------------
static __device__ __forceinline__ unsigned long long pk2(float a, float b) {
    unsigned long long v;
    asm("mov.b64 %0, {%1, %2};" : "=l"(v) : "f"(a), "f"(b));
    return v;
}
static __device__ __forceinline__ float2 upk2(unsigned long long v) {
    float2 f;
    asm("mov.b64 {%0, %1}, %2;" : "=f"(f.x), "=f"(f.y) : "l"(v));
    return f;
}
static __device__ __forceinline__ void fma2(unsigned long long& d,
                                            unsigned long long a,
                                            unsigned long long b) {
    asm("fma.rn.f32x2 %0, %1, %2, %0;" : "+l"(d) : "l"(a), "l"(b));
}

static __device__ __forceinline__ void mma16816(
    float& d0, float& d1, float& d2, float& d3,
    unsigned a0, unsigned a1, unsigned a2, unsigned a3,
    unsigned b0, unsigned b1,
    float c0, float c1, float c2, float c3) {
    asm volatile(
        "mma.sync.aligned.m16n8k16.row.col.f32.f16.f16.f32 "
        "{%0,%1,%2,%3},{%4,%5,%6,%7},{%8,%9},{%10,%11,%12,%13};"
        : "=f"(d0), "=f"(d1), "=f"(d2), "=f"(d3)
        : "r"(a0), "r"(a1), "r"(a2), "r"(a3), "r"(b0), "r"(b1),
          "f"(c0), "f"(c1), "f"(c2), "f"(c3));
}

// ---------------------------------------------------------------------------
__global__ void zero_spart_kernel() {
    int t = blockIdx.x * blockDim.x + threadIdx.x;
    if (t < 3 * B * ND) ((float*)g_spart)[t] = 0.0f;
}

__global__ void cvt_x_kernel(const float4* __restrict__ src) {
    int t = blockIdx.x * blockDim.x + threadIdx.x;  // < 524288
    float4 f = src[t];
    __half2 h0 = __floats2half2_rn(f.x, f.y);
    __half2 h1 = __floats2half2_rn(f.z, f.w);
    uint2 o;
    o.x = *reinterpret_cast<unsigned*>(&h0);
    o.y = *reinterpret_cast<unsigned*>(&h1);
    reinterpret_cast<uint2*>(g_xh)[t] = o;
}

// ---------------------------------------------------------------------------
// Kernel B: s0 GEMM (s0[b,r] = sum_{j,i} x W) + W fp32->fp16 conversion.
// grid 64 (jtile=32), block 256 (8 warps). Warp w: r in [64w, 64w+64), M=64.
// Per j: stream W_j fp32 (coalesced), write g_Wh fp16 + stage fp16 in smem,
// mma-accumulate into C regs across all 32 j; flush once via atomics.
// ---------------------------------------------------------------------------
#define WSP 24  // Ws row pitch in halves (conflict-free frag loads)
__global__ void __launch_bounds__(256, 1)
k_s0cvt_kernel(const float4* __restrict__ Wf4) {
    __shared__ __half Ws[512 * WSP];  // 24 KB

    const int tid = threadIdx.x;
    const int w = tid >> 5;
    const int lane = tid & 31;
    const int gid = lane >> 2;
    const int tig = lane & 3;
    const int j0 = blockIdx.x * 32;

    float C[8][4][4];
#pragma unroll
    for (int nt = 0; nt < 8; ++nt)
#pragma unroll
        for (int mi = 0; mi < 4; ++mi)
#pragma unroll
            for (int e = 0; e < 4; ++e) C[nt][mi][e] = 0.0f;

    for (int jj = 0; jj < 32; ++jj) {
        const int j = j0 + jj;
        if (jj) __syncthreads();  // protect Ws reuse
        // convert + stage W_j: 512 rows x 16 i fp32 -> fp16
#pragma unroll
        for (int p = 0; p < 8; ++p) {
            int e = (p << 8) + tid;        // 0..2047
            int n = e >> 6;
            int rem = e & 63;              // d*4 + i/4 quarters
            float4 f = Wf4[((size_t)(n * J + j)) * 64 + rem];
            __half2 h0 = __floats2half2_rn(f.x, f.y);
            __half2 h1 = __floats2half2_rn(f.z, f.w);
            uint2 o;
            o.x = *reinterpret_cast<unsigned*>(&h0);
            o.y = *reinterpret_cast<unsigned*>(&h1);
            reinterpret_cast<uint2*>(g_Wh)[((size_t)(n * J + j)) * 64 + rem] = o;
            int r = (n << 4) + (rem >> 2);
            int iq = rem & 3;
            *reinterpret_cast<uint2*>(&Ws[r * WSP + iq * 4]) = o;
        }
        __syncthreads();

        // A fragments from g_xh (L1-resident 2KB slab)
        unsigned a[4][4];
#pragma unroll
        for (int mi = 0; mi < 4; ++mi) {
            const __half* x0 = g_xh + (((size_t)((mi * 16 + gid) * J + j)) << 4);
            const __half* x1 = g_xh + (((size_t)((mi * 16 + gid + 8) * J + j)) << 4);
            a[mi][0] = *reinterpret_cast<const unsigned*>(x0 + 2 * tig);
            a[mi][1] = *reinterpret_cast<const unsigned*>(x1 + 2 * tig);
            a[mi][2] = *reinterpret_cast<const unsigned*>(x0 + 2 * tig + 8);
            a[mi][3] = *reinterpret_cast<const unsigned*>(x1 + 2 * tig + 8);
        }

#pragma unroll
        for (int nt = 0; nt < 8; ++nt) {
            const int r = 64 * w + nt * 8 + gid;
            unsigned b0 = *reinterpret_cast<const unsigned*>(&Ws[r * WSP + 2 * tig]);
            unsigned b1 = *reinterpret_cast<const unsigned*>(&Ws[r * WSP + 2 * tig + 8]);
#pragma unroll
            for (int mi = 0; mi < 4; ++mi)
                mma16816(C[nt][mi][0], C[nt][mi][1], C[nt][mi][2], C[nt][mi][3],
                         a[mi][0], a[mi][1], a[mi][2], a[mi][3], b0, b1,
                         C[nt][mi][0], C[nt][mi][1], C[nt][mi][2], C[nt][mi][3]);
        }
    }

    // flush s0
#pragma unroll
    for (int nt = 0; nt < 8; ++nt) {
        const int r = 64 * w + nt * 8 + 2 * tig;
#pragma unroll
        for (int mi = 0; mi < 4; ++mi) {
            const int brow = mi * 16 + gid;
            atomicAdd(&g_spart[0][brow * ND + r],           C[nt][mi][0]);
            atomicAdd(&g_spart[0][brow * ND + r + 1],       C[nt][mi][1]);
            atomicAdd(&g_spart[0][(brow + 8) * ND + r],     C[nt][mi][2]);
            atomicAdd(&g_spart[0][(brow + 8) * ND + r + 1], C[nt][mi][3]);
        }
    }
}

// ---------------------------------------------------------------------------
// Squash kernels
// ---------------------------------------------------------------------------
__device__ __forceinline__ void squash_core(const float* s, float* out, float pre) {
    float sv[16];
    float s2 = 0.0f;
#pragma unroll
    for (int d = 0; d < 16; ++d) {
        float val = s[d] * pre;
        sv[d] = val;
        s2 = fmaf(val, val, s2);
    }
    s2 += EPS;
    float sc = sqrtf(s2) / (1.0f + s2);
#pragma unroll
    for (int d = 0; d < 16; ++d) out[d] = sc * sv[d];
}

template <int IT>
__global__ void squash_mid_kernel() {
    int t = blockIdx.x * blockDim.x + threadIdx.x;  // (b*32+n)
    if (IT == 0) {
        squash_core(&g_spart[0][t * 16], &g_v[0][t * 16], 1.0f / 32.0f);
    } else {
        float v1[16];
        squash_core(&g_spart[1][t * 16], v1, 1.0f);
#pragma unroll
        for (int d = 0; d < 16; ++d)
            g_v[1][t * 16 + d] = g_v[0][t * 16 + d] + v1[d];  // vsum = v0+v1
    }
}

__global__ void squash_out_kernel(float* __restrict__ out) {
    int t = blockIdx.x * blockDim.x + threadIdx.x;
    squash_core(&g_spart[2][t * 16], &out[t * 16], 1.0f);
}

// ---------------------------------------------------------------------------
// Fused routing pass: recompute u_hat tile via mma (W from L2), softmax over n
// through smem, accumulate s in registers. MODE 1: v=v0; MODE 2: v=v0+v1.
// grid (64 jc, 4 bg), block 256 (8 warps). Warp w: r in [64w,64w+64) = n 4w..4w+3;
// each block: 16 b (its bg), 32 j.
// ---------------------------------------------------------------------------
template <int MODE>
__global__ void __launch_bounds__(256, 1) route_fused_kernel() {
    __shared__ float ts[16 * 36];
    __shared__ float cs[16 * 36];

    const int tid = threadIdx.x;
    const int w = tid >> 5;
    const int lane = tid & 31;
    const int gid = lane >> 2;
    const int tig = lane & 3;
    const int bg = blockIdx.y;
    const int j0 = blockIdx.x * 32;

    // v registers: vr[rowhalf][q][khalf], d = 2*tig + 8*khalf + {0,1}
    unsigned long long vr[2][4][2];
#pragma unroll
    for (int bi = 0; bi < 2; ++bi) {
        const int b = bg * 16 + gid + 8 * bi;
#pragma unroll
        for (int q = 0; q < 4; ++q) {
            const int n = 4 * w + q;
#pragma unroll
            for (int h = 0; h < 2; ++h) {
                float2 f = *reinterpret_cast<const float2*>(
                    &g_v[MODE - 1][(b * 32 + n) * 16 + 2 * tig + 8 * h]);
                vr[bi][q][h] = pk2(f.x, f.y);
            }
        }
    }

    unsigned long long s2[8][2];
#pragma unroll
    for (int nt = 0; nt < 8; ++nt) { s2[nt][0] = 0ull; s2[nt][1] = 0ull; }

    for (int jj = 0; jj < 32; ++jj) {
        const int j = j0 + jj;

        // A fragments (x slab 512B, L1 hits across warps)
        const __half* x0 = g_xh + (((size_t)((bg * 16 + gid) * J + j)) << 4);
        const __half* x1 = g_xh + (((size_t)((bg * 16 + gid + 8) * J + j)) << 4);
        const unsigned a0 = *reinterpret_cast<const unsigned*>(x0 + 2 * tig);
        const unsigned a1 = *reinterpret_cast<const unsigned*>(x1 + 2 * tig);
        const unsigned a2 = *reinterpret_cast<const unsigned*>(x0 + 2 * tig + 8);
        const unsigned a3 = *reinterpret_cast<const unsigned*>(x1 + 2 * tig + 8);

        // B fragments: all 16 loads issued upfront for MLP (W is L2-resident)
        unsigned bf0[8], bf1[8];
#pragma unroll
        for (int nt = 0; nt < 8; ++nt) {
            const int r = 64 * w + nt * 8 + gid;
            const __half* wp = g_Wh + (((size_t)((r >> 4) * J + j)) << 8) + ((r & 15) << 4);
            bf0[nt] = __ldg(reinterpret_cast<const unsigned*>(wp + 2 * tig));
            bf1[nt] = __ldg(reinterpret_cast<const unsigned*>(wp + 2 * tig + 8));
        }

        float C[8][4];
#pragma unroll
        for (int nt = 0; nt < 8; ++nt) {
            mma16816(C[nt][0], C[nt][1], C[nt][2], C[nt][3],
                     a0, a1, a2, a3, bf0[nt], bf1[nt],
                     0.0f, 0.0f, 0.0f, 0.0f);
        }

        // pack C pairs
        unsigned long long p01[8], p23[8];
#pragma unroll
        for (int nt = 0; nt < 8; ++nt) {
            p01[nt] = pk2(C[nt][0], C[nt][1]);
            p23[nt] = pk2(C[nt][2], C[nt][3]);
        }

        // logits t[b,n] = v . u  (reduce over d: in-thread + tig butterfly)
        float tv0[4], tv1[4];
#pragma unroll
        for (int q = 0; q < 4; ++q) {
            unsigned long long t2 = 0ull;
            fma2(t2, p01[2 * q], vr[0][q][0]);
            fma2(t2, p01[2 * q + 1], vr[0][q][1]);
            float2 f = upk2(t2);
            float tt = f.x + f.y;
            tt += __shfl_xor_sync(0xffffffffu, tt, 1);
            tt += __shfl_xor_sync(0xffffffffu, tt, 2);
            tv0[q] = tt;

            unsigned long long u2 = 0ull;
            fma2(u2, p23[2 * q], vr[1][q][0]);
            fma2(u2, p23[2 * q + 1], vr[1][q][1]);
            float2 g = upk2(u2);
            float uu = g.x + g.y;
            uu += __shfl_xor_sync(0xffffffffu, uu, 1);
            uu += __shfl_xor_sync(0xffffffffu, uu, 2);
            tv1[q] = uu;
        }

        // stage-a: one lane per (b,n) writes t (values identical across tig)
        float w0 = tig == 0 ? tv0[0] : tig == 1 ? tv0[1] : tig == 2 ? tv0[2] : tv0[3];
        float w1 = tig == 0 ? tv1[0] : tig == 1 ? tv1[1] : tig == 2 ? tv1[2] : tv1[3];
        ts[gid * 36 + 4 * w + tig] = w0;
        ts[(gid + 8) * 36 + 4 * w + tig] = w1;
        __syncthreads();

        // stage-b: softmax over n per b (16 threads per b, 2 n each)
        {
            const int b16 = tid >> 4;
            const int s16 = tid & 15;
            float2 tt2 = *reinterpret_cast<const float2*>(&ts[b16 * 36 + 2 * s16]);
            float e0 = __expf(tt2.x);
            float e1 = __expf(tt2.y);
            float sum = e0 + e1;
            sum += __shfl_xor_sync(0xffffffffu, sum, 1);
            sum += __shfl_xor_sync(0xffffffffu, sum, 2);
            sum += __shfl_xor_sync(0xffffffffu, sum, 4);
            sum += __shfl_xor_sync(0xffffffffu, sum, 8);
            float2 cc;
            cc.x = __fdividef(e0, sum);
            cc.y = __fdividef(e1, sum);
            *reinterpret_cast<float2*>(&cs[b16 * 36 + 2 * s16]) = cc;
        }
        __syncthreads();

        // owners: s += c * u
        float4 cA = *reinterpret_cast<const float4*>(&cs[gid * 36 + 4 * w]);
        float4 cB = *reinterpret_cast<const float4*>(&cs[(gid + 8) * 36 + 4 * w]);
        const float cAa[4] = {cA.x, cA.y, cA.z, cA.w};
        const float cBa[4] = {cB.x, cB.y, cB.z, cB.w};
#pragma unroll
        for (int nt = 0; nt < 8; ++nt) {
            const int q = nt >> 1;
            fma2(s2[nt][0], pk2(cAa[q], cAa[q]), p01[nt]);
            fma2(s2[nt][1], pk2(cBa[q], cBa[q]), p23[nt]);
        }
    }

    // flush s partials
#pragma unroll
    for (int nt = 0; nt < 8; ++nt) {
        const int r = 64 * w + nt * 8 + 2 * tig;
        float2 fa = upk2(s2[nt][0]);
        float2 fb = upk2(s2[nt][1]);
        const int bA = bg * 16 + gid;
        atomicAdd(&g_spart[MODE][bA * ND + r], fa.x);
        atomicAdd(&g_spart[MODE][bA * ND + r + 1], fa.y);
        atomicAdd(&g_spart[MODE][(bA + 8) * ND + r], fb.x);
        atomicAdd(&g_spart[MODE][(bA + 8) * ND + r + 1], fb.y);
    }
}

// ---------------------------------------------------------------------------
extern "C" void kernel_launch(void* const* d_in, const int* in_sizes, int n_in,
                              void* d_out, int out_size) {
    const float* x = (const float*)d_in[0];  // [B, J, 16]
    const float* W = (const float*)d_in[1];  // [N, J, D, 16]
    float* out = (float*)d_out;              // [B, N, D]

    cvt_x_kernel<<<2048, 256>>>((const float4*)x);
    zero_spart_kernel<<<96, 1024>>>();
    k_s0cvt_kernel<<<64, 256>>>((const float4*)W);
    squash_mid_kernel<0><<<16, 128>>>();                    // v0
    route_fused_kernel<1><<<dim3(64, 4), 256>>>();          // iter 1 -> s1
    squash_mid_kernel<1><<<16, 128>>>();                    // vsum
    route_fused_kernel<2><<<dim3(64, 4), 256>>>();          // iter 2 -> s2
    squash_out_kernel<<<16, 128>>>(out);                    // v2
}

// round 5
// speedup vs baseline: 1.8933x; 1.3066x over previous
#include <cuda_runtime.h>
#include <cuda_fp16.h>
#include <math.h>

#define B 64
#define J 2048
#define N 32
#define D 16
#define ND 512
#define EPS 1e-7f

__device__ __align__(16) __half g_Wh[(size_t)N * J * D * 16];  // 33.5 MiB fp16 W
__device__ __align__(16) __half g_xh[(size_t)B * J * 16];      // 4.2 MiB fp16 x
__device__ __align__(16) float g_spart[3][B * ND];             // s accum [b][n*16+d]

// ---- helpers --------------------------------------------------------------
static __device__ __forceinline__ unsigned long long pk2(float a, float b) {
    unsigned long long v;
    asm("mov.b64 %0, {%1, %2};" : "=l"(v) : "f"(a), "f"(b));
    return v;
}
static __device__ __forceinline__ float2 upk2(unsigned long long v) {
    float2 f;
    asm("mov.b64 {%0, %1}, %2;" : "=f"(f.x), "=f"(f.y) : "l"(v));
    return f;
}
static __device__ __forceinline__ void fma2(unsigned long long& d,
                                            unsigned long long a,
                                            unsigned long long b) {
    asm("fma.rn.f32x2 %0, %1, %2, %0;" : "+l"(d) : "l"(a), "l"(b));
}
static __device__ __forceinline__ void redv2(float* p, float a, float b) {
    asm volatile("red.global.add.v2.f32 [%0], {%1, %2};"
                 :: "l"(p), "f"(a), "f"(b) : "memory");
}
static __device__ __forceinline__ void mma16816(
    float& d0, float& d1, float& d2, float& d3,
    unsigned a0, unsigned a1, unsigned a2, unsigned a3,
    unsigned b0, unsigned b1,
    float c0, float c1, float c2, float c3) {
    asm volatile(
        "mma.sync.aligned.m16n8k16.row.col.f32.f16.f16.f32 "
        "{%0,%1,%2,%3},{%4,%5,%6,%7},{%8,%9},{%10,%11,%12,%13};"
        : "=f"(d0), "=f"(d1), "=f"(d2), "=f"(d3)
        : "r"(a0), "r"(a1), "r"(a2), "r"(a3), "r"(b0), "r"(b1),
          "f"(c0), "f"(c1), "f"(c2), "f"(c3));
}

// ---------------------------------------------------------------------------
// cvt_x + zero spart (fused)
// ---------------------------------------------------------------------------
__global__ void cvt_x_zero_kernel(const float4* __restrict__ src) {
    int t = blockIdx.x * blockDim.x + threadIdx.x;  // < 524288
    float4 f = src[t];
    __half2 h0 = __floats2half2_rn(f.x, f.y);
    __half2 h1 = __floats2half2_rn(f.z, f.w);
    uint2 o;
    o.x = *reinterpret_cast<unsigned*>(&h0);
    o.y = *reinterpret_cast<unsigned*>(&h1);
    reinterpret_cast<uint2*>(g_xh)[t] = o;
    if (t < 3 * B * ND) ((float*)g_spart)[t] = 0.0f;
}

// ---------------------------------------------------------------------------
// k_s0cvt: stream W fp32, convert->fp16 (store g_Wh), mma-accumulate
// s0[b,r] = sum_{j,i} x[b,j,i] W[r,j,i]. grid 128 (jtile 16), 256 thr / 8 warps.
// warp w: r in [64w, 64w+64). No smem, no barriers. Flush via red.v2.
// ---------------------------------------------------------------------------
__global__ void __launch_bounds__(256, 1)
k_s0cvt_kernel(const float* __restrict__ Wf) {
    const int tid = threadIdx.x;
    const int w = tid >> 5;
    const int lane = tid & 31;
    const int gid = lane >> 2;
    const int tig = lane & 3;

    float C[8][4][4];
#pragma unroll
    for (int nt = 0; nt < 8; ++nt)
#pragma unroll
        for (int mi = 0; mi < 4; ++mi)
#pragma unroll
            for (int e = 0; e < 4; ++e) C[nt][mi][e] = 0.0f;

    for (int jj = 0; jj < 16; ++jj) {
        const int j = blockIdx.x * 16 + jj;

        // issue all W loads first (MLP 16)
        float2 F0[8], F1[8];
#pragma unroll
        for (int nt = 0; nt < 8; ++nt) {
            const int r = 64 * w + 8 * nt + gid;
            const float* wp = Wf + ((size_t)((r >> 4) * J + j)) * 256 + ((r & 15) << 4);
            F0[nt] = *reinterpret_cast<const float2*>(wp + 2 * tig);
            F1[nt] = *reinterpret_cast<const float2*>(wp + 2 * tig + 8);
        }

        // A fragments from g_xh
        unsigned a[4][4];
#pragma unroll
        for (int mi = 0; mi < 4; ++mi) {
            const __half* x0 = g_xh + (((size_t)((mi * 16 + gid) * J + j)) << 4);
            const __half* x1 = g_xh + (((size_t)((mi * 16 + gid + 8) * J + j)) << 4);
            a[mi][0] = *reinterpret_cast<const unsigned*>(x0 + 2 * tig);
            a[mi][1] = *reinterpret_cast<const unsigned*>(x1 + 2 * tig);
            a[mi][2] = *reinterpret_cast<const unsigned*>(x0 + 2 * tig + 8);
            a[mi][3] = *reinterpret_cast<const unsigned*>(x1 + 2 * tig + 8);
        }

#pragma unroll
        for (int nt = 0; nt < 8; ++nt) {
            const int r = 64 * w + 8 * nt + gid;
            __half2 h0 = __floats2half2_rn(F0[nt].x, F0[nt].y);
            __half2 h1 = __floats2half2_rn(F1[nt].x, F1[nt].y);
            unsigned b0 = *reinterpret_cast<unsigned*>(&h0);
            unsigned b1 = *reinterpret_cast<unsigned*>(&h1);
            __half* op = g_Wh + ((size_t)((r >> 4) * J + j)) * 256 + ((r & 15) << 4);
            *reinterpret_cast<unsigned*>(op + 2 * tig) = b0;
            *reinterpret_cast<unsigned*>(op + 2 * tig + 8) = b1;
#pragma unroll
            for (int mi = 0; mi < 4; ++mi)
                mma16816(C[nt][mi][0], C[nt][mi][1], C[nt][mi][2], C[nt][mi][3],
                         a[mi][0], a[mi][1], a[mi][2], a[mi][3], b0, b1,
                         C[nt][mi][0], C[nt][mi][1], C[nt][mi][2], C[nt][mi][3]);
        }
    }

    // flush s0 with vector reductions
#pragma unroll
    for (int nt = 0; nt < 8; ++nt) {
        const int r = 64 * w + 8 * nt + 2 * tig;
#pragma unroll
        for (int mi = 0; mi < 4; ++mi) {
            const int brow = mi * 16 + gid;
            redv2(&g_spart[0][brow * ND + r], C[nt][mi][0], C[nt][mi][1]);
            redv2(&g_spart[0][(brow + 8) * ND + r], C[nt][mi][2], C[nt][mi][3]);
        }
    }
}

// ---------------------------------------------------------------------------
// Fused routing pass with inline squash prologue and single-sync softmax.
// MODE 1: v = squash(s0/32); MODE 2: v = squash(s0/32)+squash(s1).
// grid (32 jc, 4 bg), 256 thr / 8 warps; block does 16 b x all 512 r x 64 j.
// ---------------------------------------------------------------------------
template <int MODE>
__global__ void __launch_bounds__(256, 1) route_fused_kernel() {
    __shared__ float ts[2][16][36];

    const int tid = threadIdx.x;
    const int w = tid >> 5;
    const int lane = tid & 31;
    const int gid = lane >> 2;
    const int tig = lane & 3;
    const int bg = blockIdx.y;
    const int j0 = blockIdx.x * 64;

    // --- prologue: squash(s) -> v in registers -----------------------------
    unsigned long long vr[2][4][2];
#pragma unroll
    for (int bi = 0; bi < 2; ++bi) {
#pragma unroll
        for (int q = 0; q < 4; ++q) {
            const int b = bg * 16 + gid + 8 * bi;
            const int n = 4 * w + q;
            float vx0 = 0.f, vy0 = 0.f, vx1 = 0.f, vy1 = 0.f;
#pragma unroll
            for (int it = 0; it < MODE; ++it) {
                const float pre = (it == 0) ? (1.0f / 32.0f) : 1.0f;
                const float* sp = &g_spart[it][(b * 32 + n) * 16];
                float2 f0 = *reinterpret_cast<const float2*>(sp + 2 * tig);
                float2 f1 = *reinterpret_cast<const float2*>(sp + 8 + 2 * tig);
                f0.x *= pre; f0.y *= pre; f1.x *= pre; f1.y *= pre;
                float p = f0.x * f0.x + f0.y * f0.y + f1.x * f1.x + f1.y * f1.y;
                p += __shfl_xor_sync(0xffffffffu, p, 1);
                p += __shfl_xor_sync(0xffffffffu, p, 2);
                p += EPS;
                float sc = sqrtf(p) / (1.0f + p);
                vx0 += sc * f0.x; vy0 += sc * f0.y;
                vx1 += sc * f1.x; vy1 += sc * f1.y;
            }
            vr[bi][q][0] = pk2(vx0, vy0);
            vr[bi][q][1] = pk2(vx1, vy1);
        }
    }

    unsigned long long s2[8][2];
#pragma unroll
    for (int nt = 0; nt < 8; ++nt) { s2[nt][0] = 0ull; s2[nt][1] = 0ull; }

    unsigned bufA0[8], bufA1[8], bufB0[8], bufB1[8];

#define LOADW(jv, d0, d1)                                                      \
    {                                                                          \
        _Pragma("unroll") for (int nt = 0; nt < 8; ++nt) {                     \
            const int r = 64 * w + 8 * nt + gid;                               \
            const __half* wp =                                                 \
                g_Wh + ((size_t)((r >> 4) * J + (jv))) * 256 + ((r & 15) << 4);\
            d0[nt] = __ldg(reinterpret_cast<const unsigned*>(wp + 2 * tig));   \
            d1[nt] = __ldg(reinterpret_cast<const unsigned*>(wp + 2 * tig + 8));\
        }                                                                      \
    }

#define BODY(jj, c0, c1, n0, n1, par)                                          \
    {                                                                          \
        const int j = j0 + (jj);                                               \
        const __half* x0 = g_xh + (((size_t)((bg * 16 + gid) * J + j)) << 4);  \
        const __half* x1 = g_xh + (((size_t)((bg * 16 + gid + 8) * J + j)) << 4);\
        const unsigned a0 = *reinterpret_cast<const unsigned*>(x0 + 2 * tig);  \
        const unsigned a1 = *reinterpret_cast<const unsigned*>(x1 + 2 * tig);  \
        const unsigned a2 = *reinterpret_cast<const unsigned*>(x0 + 2 * tig + 8);\
        const unsigned a3 = *reinterpret_cast<const unsigned*>(x1 + 2 * tig + 8);\
        if ((jj) < 63) LOADW(j + 1, n0, n1);                                   \
        unsigned long long p01[8], p23[8];                                     \
        _Pragma("unroll") for (int nt = 0; nt < 8; ++nt) {                     \
            float d0, d1, d2, d3;                                              \
            mma16816(d0, d1, d2, d3, a0, a1, a2, a3, c0[nt], c1[nt],           \
                     0.0f, 0.0f, 0.0f, 0.0f);                                  \
            p01[nt] = pk2(d0, d1);                                             \
            p23[nt] = pk2(d2, d3);                                             \
        }                                                                      \
        float tv0[4], tv1[4];                                                  \
        _Pragma("unroll") for (int q = 0; q < 4; ++q) {                        \
            unsigned long long t2 = 0ull;                                      \
            fma2(t2, p01[2 * q], vr[0][q][0]);                                 \
            fma2(t2, p01[2 * q + 1], vr[0][q][1]);                             \
            float2 f = upk2(t2);                                               \
            float tt = f.x + f.y;                                              \
            tt += __shfl_xor_sync(0xffffffffu, tt, 1);                         \
            tt += __shfl_xor_sync(0xffffffffu, tt, 2);                         \
            tv0[q] = tt;                                                       \
            unsigned long long u2 = 0ull;                                      \
            fma2(u2, p23[2 * q], vr[1][q][0]);                                 \
            fma2(u2, p23[2 * q + 1], vr[1][q][1]);                             \
            float2 g = upk2(u2);                                               \
            float uu = g.x + g.y;                                              \
            uu += __shfl_xor_sync(0xffffffffu, uu, 1);                         \
            uu += __shfl_xor_sync(0xffffffffu, uu, 2);                         \
            tv1[q] = uu;                                                       \
        }                                                                      \
        float e0 = __expf(tig == 0 ? tv0[0] : tig == 1 ? tv0[1]                \
                                  : tig == 2 ? tv0[2] : tv0[3]);               \
        float e1 = __expf(tig == 0 ? tv1[0] : tig == 1 ? tv1[1]                \
                                  : tig == 2 ? tv1[2] : tv1[3]);               \
        ts[par][gid][4 * w + tig] = e0;                                        \
        ts[par][gid + 8][4 * w + tig] = e1;                                    \
        __syncthreads();                                                       \
        float4 sa0 = *reinterpret_cast<const float4*>(&ts[par][gid][tig * 8]); \
        float4 sa1 = *reinterpret_cast<const float4*>(&ts[par][gid][tig * 8 + 4]);\
        float4 sb0 = *reinterpret_cast<const float4*>(&ts[par][gid + 8][tig * 8]);\
        float4 sb1 = *reinterpret_cast<const float4*>(&ts[par][gid + 8][tig * 8 + 4]);\
        float SA = sa0.x + sa0.y + sa0.z + sa0.w + sa1.x + sa1.y + sa1.z + sa1.w;\
        float SB = sb0.x + sb0.y + sb0.z + sb0.w + sb1.x + sb1.y + sb1.z + sb1.w;\
        SA += __shfl_xor_sync(0xffffffffu, SA, 1);                             \
        SA += __shfl_xor_sync(0xffffffffu, SA, 2);                             \
        SB += __shfl_xor_sync(0xffffffffu, SB, 1);                             \
        SB += __shfl_xor_sync(0xffffffffu, SB, 2);                             \
        float rA = __fdividef(1.0f, SA);                                       \
        float rB = __fdividef(1.0f, SB);                                       \
        float4 eA = *reinterpret_cast<const float4*>(&ts[par][gid][4 * w]);    \
        float4 eB = *reinterpret_cast<const float4*>(&ts[par][gid + 8][4 * w]);\
        const float cAa[4] = {eA.x * rA, eA.y * rA, eA.z * rA, eA.w * rA};     \
        const float cBa[4] = {eB.x * rB, eB.y * rB, eB.z * rB, eB.w * rB};     \
        _Pragma("unroll") for (int nt = 0; nt < 8; ++nt) {                     \
            const int q = nt >> 1;                                             \
            fma2(s2[nt][0], pk2(cAa[q], cAa[q]), p01[nt]);                     \
            fma2(s2[nt][1], pk2(cBa[q], cBa[q]), p23[nt]);                     \
        }                                                                      \
    }

    LOADW(j0, bufA0, bufA1);
    for (int jp = 0; jp < 32; ++jp) {
        BODY(2 * jp, bufA0, bufA1, bufB0, bufB1, 0);
        BODY(2 * jp + 1, bufB0, bufB1, bufA0, bufA1, 1);
    }
#undef BODY
#undef LOADW

    // flush s partials
    const int bA = bg * 16 + gid;
#pragma unroll
    for (int nt = 0; nt < 8; ++nt) {
        const int r = 64 * w + 8 * nt + 2 * tig;
        float2 fa = upk2(s2[nt][0]);
        float2 fb = upk2(s2[nt][1]);
        redv2(&g_spart[MODE][bA * ND + r], fa.x, fa.y);
        redv2(&g_spart[MODE][(bA + 8) * ND + r], fb.x, fb.y);
    }
}

// ---------------------------------------------------------------------------
__global__ void squash_out_kernel(float* __restrict__ out) {
    int t = blockIdx.x * blockDim.x + threadIdx.x;  // (b*32+n)
    const float* s = &g_spart[2][t * 16];
    float sv[16];
    float s2 = 0.0f;
#pragma unroll
    for (int d = 0; d < 16; ++d) {
        float val = s[d];
        sv[d] = val;
        s2 = fmaf(val, val, s2);
    }
    s2 += EPS;
    float sc = sqrtf(s2) / (1.0f + s2);
#pragma unroll
    for (int d = 0; d < 16; ++d) out[t * 16 + d] = sc * sv[d];
}

// ---------------------------------------------------------------------------
extern "C" void kernel_launch(void* const* d_in, const int* in_sizes, int n_in,
                              void* d_out, int out_size) {
    const float* x = (const float*)d_in[0];  // [B, J, 16]
    const float* W = (const float*)d_in[1];  // [N, J, D, 16]
    float* out = (float*)d_out;              // [B, N, D]

    cvt_x_zero_kernel<<<2048, 256>>>((const float4*)x);
    k_s0cvt_kernel<<<128, 256>>>(W);
    route_fused_kernel<1><<<dim3(32, 4), 256>>>();
    route_fused_kernel<2><<<dim3(32, 4), 256>>>();
    squash_out_kernel<<<16, 128>>>(out);
}

// round 6
// speedup vs baseline: 1.9962x; 1.0543x over previous
#include <cuda_runtime.h>
#include <cuda_fp16.h>
#include <math.h>

#define B 64
#define J 2048
#define N 32
#define D 16
#define ND 512
#define EPS 1e-7f

__device__ __align__(16) __half g_Wh[(size_t)N * J * D * 16];  // 33.5 MiB fp16 W
__device__ __align__(16) __half g_xh[(size_t)B * J * 16];      // 4.2 MiB fp16 x
__device__ __align__(16) float g_spart[3][B * ND];             // s accum [b][n*16+d]

// ---- helpers --------------------------------------------------------------
static __device__ __forceinline__ unsigned long long pk2(float a, float b) {
    unsigned long long v;
    asm("mov.b64 %0, {%1, %2};" : "=l"(v) : "f"(a), "f"(b));
    return v;
}
static __device__ __forceinline__ float2 upk2(unsigned long long v) {
    float2 f;
    asm("mov.b64 {%0, %1}, %2;" : "=f"(f.x), "=f"(f.y) : "l"(v));
    return f;
}
static __device__ __forceinline__ void fma2(unsigned long long& d,
                                            unsigned long long a,
                                            unsigned long long b) {
    asm("fma.rn.f32x2 %0, %1, %2, %0;" : "+l"(d) : "l"(a), "l"(b));
}
static __device__ __forceinline__ void redv2(float* p, float a, float b) {
    asm volatile("red.global.add.v2.f32 [%0], {%1, %2};"
                 :: "l"(p), "f"(a), "f"(b) : "memory");
}
static __device__ __forceinline__ void mma16816(
    float& d0, float& d1, float& d2, float& d3,
    unsigned a0, unsigned a1, unsigned a2, unsigned a3,
    unsigned b0, unsigned b1,
    float c0, float c1, float c2, float c3) {
    asm volatile(
        "mma.sync.aligned.m16n8k16.row.col.f32.f16.f16.f32 "
        "{%0,%1,%2,%3},{%4,%5,%6,%7},{%8,%9},{%10,%11,%12,%13};"
        : "=f"(d0), "=f"(d1), "=f"(d2), "=f"(d3)
        : "r"(a0), "r"(a1), "r"(a2), "r"(a3), "r"(b0), "r"(b1),
          "f"(c0), "f"(c1), "f"(c2), "f"(c3));
}

// ---------------------------------------------------------------------------
__global__ void cvt_x_zero_kernel(const float4* __restrict__ src) {
    int t = blockIdx.x * blockDim.x + threadIdx.x;  // < 524288
    float4 f = src[t];
    __half2 h0 = __floats2half2_rn(f.x, f.y);
    __half2 h1 = __floats2half2_rn(f.z, f.w);
    uint2 o;
    o.x = *reinterpret_cast<unsigned*>(&h0);
    o.y = *reinterpret_cast<unsigned*>(&h1);
    reinterpret_cast<uint2*>(g_xh)[t] = o;
    if (t < 3 * B * ND) ((float*)g_spart)[t] = 0.0f;
}

// ---------------------------------------------------------------------------
// k_s0cvt: stream W fp32, convert->fp16 (store g_Wh), mma-accumulate s0.
// ---------------------------------------------------------------------------
__global__ void __launch_bounds__(256, 1)
k_s0cvt_kernel(const float* __restrict__ Wf) {
    const int tid = threadIdx.x;
    const int w = tid >> 5;
    const int lane = tid & 31;
    const int gid = lane >> 2;
    const int tig = lane & 3;

    float C[8][4][4];
#pragma unroll
    for (int nt = 0; nt < 8; ++nt)
#pragma unroll
        for (int mi = 0; mi < 4; ++mi)
#pragma unroll
            for (int e = 0; e < 4; ++e) C[nt][mi][e] = 0.0f;

    for (int jj = 0; jj < 16; ++jj) {
        const int j = blockIdx.x * 16 + jj;

        float2 F0[8], F1[8];
#pragma unroll
        for (int nt = 0; nt < 8; ++nt) {
            const int r = 64 * w + 8 * nt + gid;
            const float* wp = Wf + ((size_t)((r >> 4) * J + j)) * 256 + ((r & 15) << 4);
            F0[nt] = *reinterpret_cast<const float2*>(wp + 2 * tig);
            F1[nt] = *reinterpret_cast<const float2*>(wp + 2 * tig + 8);
        }

        unsigned a[4][4];
#pragma unroll
        for (int mi = 0; mi < 4; ++mi) {
            const __half* x0 = g_xh + (((size_t)((mi * 16 + gid) * J + j)) << 4);
            const __half* x1 = g_xh + (((size_t)((mi * 16 + gid + 8) * J + j)) << 4);
            a[mi][0] = *reinterpret_cast<const unsigned*>(x0 + 2 * tig);
            a[mi][1] = *reinterpret_cast<const unsigned*>(x1 + 2 * tig);
            a[mi][2] = *reinterpret_cast<const unsigned*>(x0 + 2 * tig + 8);
            a[mi][3] = *reinterpret_cast<const unsigned*>(x1 + 2 * tig + 8);
        }

#pragma unroll
        for (int nt = 0; nt < 8; ++nt) {
            const int r = 64 * w + 8 * nt + gid;
            __half2 h0 = __floats2half2_rn(F0[nt].x, F0[nt].y);
            __half2 h1 = __floats2half2_rn(F1[nt].x, F1[nt].y);
            unsigned b0 = *reinterpret_cast<unsigned*>(&h0);
            unsigned b1 = *reinterpret_cast<unsigned*>(&h1);
            __half* op = g_Wh + ((size_t)((r >> 4) * J + j)) * 256 + ((r & 15) << 4);
            *reinterpret_cast<unsigned*>(op + 2 * tig) = b0;
            *reinterpret_cast<unsigned*>(op + 2 * tig + 8) = b1;
#pragma unroll
            for (int mi = 0; mi < 4; ++mi)
                mma16816(C[nt][mi][0], C[nt][mi][1], C[nt][mi][2], C[nt][mi][3],
                         a[mi][0], a[mi][1], a[mi][2], a[mi][3], b0, b1,
                         C[nt][mi][0], C[nt][mi][1], C[nt][mi][2], C[nt][mi][3]);
        }
    }

#pragma unroll
    for (int nt = 0; nt < 8; ++nt) {
        const int r = 64 * w + 8 * nt + 2 * tig;
#pragma unroll
        for (int mi = 0; mi < 4; ++mi) {
            const int brow = mi * 16 + gid;
            redv2(&g_spart[0][brow * ND + r], C[nt][mi][0], C[nt][mi][1]);
            redv2(&g_spart[0][(brow + 8) * ND + r], C[nt][mi][2], C[nt][mi][3]);
        }
    }
}

// ---------------------------------------------------------------------------
// Fused routing pass: 2 j per sync round, parity-alternating exchange buffers,
// cross-round W prefetch, exact 2-wave grid (296 blocks).
// MODE 1: v = squash(s0/32); MODE 2: v = squash(s0/32)+squash(s1).
// ---------------------------------------------------------------------------
template <int MODE>
__global__ void __launch_bounds__(256, 1) route_fused_kernel() {
    __shared__ float ts[2][2][16][36];

    const int tid = threadIdx.x;
    const int w = tid >> 5;
    const int lane = tid & 31;
    const int gid = lane >> 2;
    const int tig = lane & 3;
    const int bg = blockIdx.x & 3;
    const int cid = blockIdx.x >> 2;  // 0..73

    int jstart, rounds;
    if (cid < 62) { jstart = 28 * cid; rounds = 14; }
    else { jstart = 1736 + 26 * (cid - 62); rounds = 13; }

    // --- prologue: squash(s) -> v in registers -----------------------------
    unsigned long long vr[2][4][2];
#pragma unroll
    for (int bi = 0; bi < 2; ++bi) {
#pragma unroll
        for (int q = 0; q < 4; ++q) {
            const int b = bg * 16 + gid + 8 * bi;
            const int n = 4 * w + q;
            float vx0 = 0.f, vy0 = 0.f, vx1 = 0.f, vy1 = 0.f;
#pragma unroll
            for (int it = 0; it < MODE; ++it) {
                const float pre = (it == 0) ? (1.0f / 32.0f) : 1.0f;
                const float* sp = &g_spart[it][(b * 32 + n) * 16];
                float2 f0 = *reinterpret_cast<const float2*>(sp + 2 * tig);
                float2 f1 = *reinterpret_cast<const float2*>(sp + 8 + 2 * tig);
                f0.x *= pre; f0.y *= pre; f1.x *= pre; f1.y *= pre;
                float p = f0.x * f0.x + f0.y * f0.y + f1.x * f1.x + f1.y * f1.y;
                p += __shfl_xor_sync(0xffffffffu, p, 1);
                p += __shfl_xor_sync(0xffffffffu, p, 2);
                p += EPS;
                float sc = sqrtf(p) / (1.0f + p);
                vx0 += sc * f0.x; vy0 += sc * f0.y;
                vx1 += sc * f1.x; vy1 += sc * f1.y;
            }
            vr[bi][q][0] = pk2(vx0, vy0);
            vr[bi][q][1] = pk2(vx1, vy1);
        }
    }

    unsigned long long s2[8][2];
#pragma unroll
    for (int nt = 0; nt < 8; ++nt) { s2[nt][0] = 0ull; s2[nt][1] = 0ull; }

    unsigned A0[8], A1[8], B0[8], B1[8];
    unsigned long long p01a[8], p23a[8], p01b[8], p23b[8];

#define LOADW(jv, d0, d1)                                                      \
    {                                                                          \
        const int jc_ = (jv) > (J - 1) ? (J - 1) : (jv);                       \
        _Pragma("unroll") for (int nt = 0; nt < 8; ++nt) {                     \
            const int r = 64 * w + 8 * nt + gid;                               \
            const __half* wp =                                                 \
                g_Wh + ((size_t)((r >> 4) * J + jc_)) * 256 + ((r & 15) << 4); \
            d0[nt] = __ldg(reinterpret_cast<const unsigned*>(wp + 2 * tig));   \
            d1[nt] = __ldg(reinterpret_cast<const unsigned*>(wp + 2 * tig + 8));\
        }                                                                      \
    }

// Produce: mma + logits + exp -> ts[par][jp]; prefetch next pair into c0/c1
#define PRODUCE(jv, c0, c1, P01, P23, par, jp, DO_PF)                          \
    {                                                                          \
        const int j = (jv);                                                    \
        const __half* x0 = g_xh + (((size_t)((bg * 16 + gid) * J + j)) << 4);  \
        const __half* x1 = g_xh + (((size_t)((bg * 16 + gid + 8) * J + j)) << 4);\
        const unsigned a0 = *reinterpret_cast<const unsigned*>(x0 + 2 * tig);  \
        const unsigned a1 = *reinterpret_cast<const unsigned*>(x1 + 2 * tig);  \
        const unsigned a2 = *reinterpret_cast<const unsigned*>(x0 + 2 * tig + 8);\
        const unsigned a3 = *reinterpret_cast<const unsigned*>(x1 + 2 * tig + 8);\
        _Pragma("unroll") for (int nt = 0; nt < 8; ++nt) {                     \
            float d0, d1, d2, d3;                                              \
            mma16816(d0, d1, d2, d3, a0, a1, a2, a3, c0[nt], c1[nt],           \
                     0.0f, 0.0f, 0.0f, 0.0f);                                  \
            P01[nt] = pk2(d0, d1);                                             \
            P23[nt] = pk2(d2, d3);                                             \
        }                                                                      \
        if (DO_PF) LOADW(j + 2, c0, c1);                                       \
        float tv0[4], tv1[4];                                                  \
        _Pragma("unroll") for (int q = 0; q < 4; ++q) {                        \
            unsigned long long t2 = 0ull;                                      \
            fma2(t2, P01[2 * q], vr[0][q][0]);                                 \
            fma2(t2, P01[2 * q + 1], vr[0][q][1]);                             \
            float2 f = upk2(t2);                                               \
            float tt = f.x + f.y;                                              \
            tt += __shfl_xor_sync(0xffffffffu, tt, 1);                         \
            tt += __shfl_xor_sync(0xffffffffu, tt, 2);                         \
            tv0[q] = tt;                                                       \
            unsigned long long u2 = 0ull;                                      \
            fma2(u2, P23[2 * q], vr[1][q][0]);                                 \
            fma2(u2, P23[2 * q + 1], vr[1][q][1]);                             \
            float2 g = upk2(u2);                                               \
            float uu = g.x + g.y;                                              \
            uu += __shfl_xor_sync(0xffffffffu, uu, 1);                         \
            uu += __shfl_xor_sync(0xffffffffu, uu, 2);                         \
            tv1[q] = uu;                                                       \
        }                                                                      \
        float e0 = __expf(tig == 0 ? tv0[0] : tig == 1 ? tv0[1]                \
                                  : tig == 2 ? tv0[2] : tv0[3]);               \
        float e1 = __expf(tig == 0 ? tv1[0] : tig == 1 ? tv1[1]                \
                                  : tig == 2 ? tv1[2] : tv1[3]);               \
        ts[par][jp][gid][4 * w + tig] = e0;                                    \
        ts[par][jp][gid + 8][4 * w + tig] = e1;                                \
    }

#define CONSUME(par, jp, P01, P23)                                             \
    {                                                                          \
        float4 sa0 = *reinterpret_cast<const float4*>(&ts[par][jp][gid][tig * 8]);\
        float4 sa1 = *reinterpret_cast<const float4*>(&ts[par][jp][gid][tig * 8 + 4]);\
        float4 sb0 = *reinterpret_cast<const float4*>(&ts[par][jp][gid + 8][tig * 8]);\
        float4 sb1 = *reinterpret_cast<const float4*>(&ts[par][jp][gid + 8][tig * 8 + 4]);\
        float SA = sa0.x + sa0.y + sa0.z + sa0.w + sa1.x + sa1.y + sa1.z + sa1.w;\
        float SB = sb0.x + sb0.y + sb0.z + sb0.w + sb1.x + sb1.y + sb1.z + sb1.w;\
        SA += __shfl_xor_sync(0xffffffffu, SA, 1);                             \
        SA += __shfl_xor_sync(0xffffffffu, SA, 2);                             \
        SB += __shfl_xor_sync(0xffffffffu, SB, 1);                             \
        SB += __shfl_xor_sync(0xffffffffu, SB, 2);                             \
        float rA = __fdividef(1.0f, SA);                                       \
        float rB = __fdividef(1.0f, SB);                                       \
        float4 eA = *reinterpret_cast<const float4*>(&ts[par][jp][gid][4 * w]);\
        float4 eB = *reinterpret_cast<const float4*>(&ts[par][jp][gid + 8][4 * w]);\
        const float cAa[4] = {eA.x * rA, eA.y * rA, eA.z * rA, eA.w * rA};     \
        const float cBa[4] = {eB.x * rB, eB.y * rB, eB.z * rB, eB.w * rB};     \
        _Pragma("unroll") for (int nt = 0; nt < 8; ++nt) {                     \
            const int q = nt >> 1;                                             \
            fma2(s2[nt][0], pk2(cAa[q], cAa[q]), P01[nt]);                     \
            fma2(s2[nt][1], pk2(cBa[q], cBa[q]), P23[nt]);                     \
        }                                                                      \
    }

    LOADW(jstart, A0, A1);
    LOADW(jstart + 1, B0, B1);

    for (int rd = 0; rd < rounds; ++rd) {
        const int j0 = jstart + 2 * rd;
        const int par = rd & 1;
        const int pf = (rd + 1 < rounds);
        PRODUCE(j0, A0, A1, p01a, p23a, par, 0, pf);
        PRODUCE(j0 + 1, B0, B1, p01b, p23b, par, 1, pf);
        __syncthreads();
        CONSUME(par, 0, p01a, p23a);
        CONSUME(par, 1, p01b, p23b);
    }
#undef PRODUCE
#undef CONSUME
#undef LOADW

    // flush s partials
    const int bA = bg * 16 + gid;
#pragma unroll
    for (int nt = 0; nt < 8; ++nt) {
        const int r = 64 * w + 8 * nt + 2 * tig;
        float2 fa = upk2(s2[nt][0]);
        float2 fb = upk2(s2[nt][1]);
        redv2(&g_spart[MODE][bA * ND + r], fa.x, fa.y);
        redv2(&g_spart[MODE][(bA + 8) * ND + r], fb.x, fb.y);
    }
}

// ---------------------------------------------------------------------------
__global__ void squash_out_kernel(float* __restrict__ out) {
    int t = blockIdx.x * blockDim.x + threadIdx.x;  // (b*32+n)
    const float* s = &g_spart[2][t * 16];
    float sv[16];
    float s2 = 0.0f;
#pragma unroll
    for (int d = 0; d < 16; ++d) {
        float val = s[d];
        sv[d] = val;
        s2 = fmaf(val, val, s2);
    }
    s2 += EPS;
    float sc = sqrtf(s2) / (1.0f + s2);
#pragma unroll
    for (int d = 0; d < 16; ++d) out[t * 16 + d] = sc * sv[d];
}

// ---------------------------------------------------------------------------
extern "C" void kernel_launch(void* const* d_in, const int* in_sizes, int n_in,
                              void* d_out, int out_size) {
    const float* x = (const float*)d_in[0];  // [B, J, 16]
    const float* W = (const float*)d_in[1];  // [N, J, D, 16]
    float* out = (float*)d_out;              // [B, N, D]

    cvt_x_zero_kernel<<<2048, 256>>>((const float4*)x);
    k_s0cvt_kernel<<<128, 256>>>(W);
    route_fused_kernel<1><<<296, 256>>>();
    route_fused_kernel<2><<<296, 256>>>();
    squash_out_kernel<<<16, 128>>>(out);
}